// round 15
// baseline (speedup 1.0000x reference)
#include <cuda_runtime.h>
#include <cuda_fp16.h>
#include <cstdint>

#define Bq 256
#define Pq 128
#define Kq 16
#define Hq 128
#define Oq 256
#define LDH 136            // A/B tile row stride (halves); 272 bytes

__device__ int  g_idx [Bq*Pq*Kq];
__device__ __align__(256) __half g_base[Bq*Pq*Hq];
__device__ __align__(256) __half g_y   [Bq*Pq*Hq];
__device__ __align__(16)  __half g_wH  [Oq*LDH];   // W2^T fp16 [n][k]
__device__ int g_cnt;
__device__ int g_list[Bq*Pq];

// ---------------- K1: exact KNN (top-17, ties->lower idx, drop self) -------
__global__ __launch_bounds__(64) void knn_kernel(const float* __restrict__ x) {
    const int b = blockIdx.x, half = blockIdx.y, t = threadIdx.x;
    __shared__ float scx[Pq], scy[Pq], sval[Pq];
    __shared__ float sdist[64 * 130];
    for (int j = t; j < Pq; j += 64) {
        const float* row = x + ((size_t)b * Pq + j) * 10;
        scx[j] = row[0]; scy[j] = row[1]; sval[j] = row[9];
    }
    __syncthreads();
    const int p = half * 64 + t;
    if (sval[p] <= 0.f) return;
    const float cx = scx[p], cy = scy[p];
    float* drow = sdist + t * 130;
    for (int j = 0; j < Pq; j += 2) {
        float dx0 = scx[j] - cx,     dy0 = scy[j] - cy;
        float dx1 = scx[j + 1] - cx, dy1 = scy[j + 1] - cy;
        float d0 = dx0 * dx0 + dy0 * dy0;
        float d1 = dx1 * dx1 + dy1 * dy1;
        if (sval[j] <= 0.f)     d0 = 1e9f;
        if (sval[j + 1] <= 0.f) d1 = 1e9f;
        *(float2*)(drow + j) = make_float2(d0, d1);
    }
    const int off = (b * Pq + p) * Kq;
    #pragma unroll 1
    for (int pass = 0; pass < Kq + 1; pass++) {
        float best = 3.0e38f; int bj = 0;
        for (int j = 0; j < Pq; j += 2) {
            float2 d = *(const float2*)(drow + j);
            if (d.x < best) { best = d.x; bj = j; }
            if (d.y < best) { best = d.y; bj = j + 1; }
        }
        drow[bj] = 3.4e38f;
        if (pass >= 1) g_idx[off + pass - 1] = bj;
    }
}

// ---------------- K2: layer-1 factorization -> fp16; list + dead-zero fused
__global__ __launch_bounds__(256) void embed_kernel(const float* __restrict__ x,
                                                    const float* __restrict__ W1,
                                                    const float* __restrict__ b1,
                                                    float* __restrict__ out) {
    __shared__ float sx[8][10];
    const int tid = threadIdx.x;
    const int h = tid & 127, gsel = tid >> 7;
    const int p0 = blockIdx.x * 8;

    for (int i = tid; i < 80; i += 256) sx[i / 10][i % 10] = x[(size_t)p0 * 10 + i];
    float wa[9], wb[9];
    #pragma unroll
    for (int e = 0; e < 9; e++) {
        float a = W1[e * Hq + h], b = W1[(e + 9) * Hq + h];
        wa[e] = a - b; wb[e] = b;
    }
    const float bb = b1[h];
    __syncthreads();

    if (tid < 8 && sx[tid][9] > 0.f) {
        int s = atomicAdd(&g_cnt, 1);
        g_list[s] = p0 + tid;
    }
    #pragma unroll
    for (int q = 0; q < 4; q++) {
        const int lp = gsel * 4 + q;
        const int bp = p0 + lp;
        float base = bb, y = 0.f;
        #pragma unroll
        for (int e = 0; e < 9; e++) {
            float v = sx[lp][e];
            base = fmaf(v, wa[e], base);
            y    = fmaf(v, wb[e], y);
        }
        g_base[(size_t)bp * Hq + h] = __float2half_rn(base);
        g_y   [(size_t)bp * Hq + h] = __float2half_rn(y);
    }
    #pragma unroll 1
    for (int lp = 0; lp < 8; lp++) {          // zero dead output rows
        if (sx[lp][9] > 0.f) continue;
        float* orow = out + (size_t)(p0 + lp) * (Oq + 1);
        for (int i = tid; i < Oq + 1; i += 256) orow[i] = 0.f;
    }
}

// ---------------- prep: W2 -> fp16, transposed [n][k] + pad; reset list ----
__global__ __launch_bounds__(128) void prep_kernel(const float* __restrict__ W2) {
    const int i = blockIdx.x * 128 + threadIdx.x;   // i = k*256 + n
    if (i == 0) g_cnt = 0;
    g_list[i] = 0;                                  // pad slots -> point 0 (always live)
    const int k = i >> 8, n = i & 255;
    g_wH[n * LDH + k] = __float2half_rn(W2[i]);
}

// ---------------- helpers --------------------------------------------------
__device__ __forceinline__ uint32_t smem_u32(const void* p) {
    uint32_t a;
    asm("{ .reg .u64 t; cvta.to.shared.u64 t, %1; cvt.u32.u64 %0, t; }" : "=r"(a) : "l"(p));
    return a;
}
__device__ __forceinline__ void mma_f16(float* d, const unsigned* a,
                                        unsigned b0, unsigned b1) {
    asm volatile(
        "mma.sync.aligned.m16n8k16.row.col.f32.f16.f16.f32 "
        "{%0,%1,%2,%3},{%4,%5,%6,%7},{%8,%9},{%0,%1,%2,%3};"
        : "+f"(d[0]), "+f"(d[1]), "+f"(d[2]), "+f"(d[3])
        : "r"(a[0]), "r"(a[1]), "r"(a[2]), "r"(a[3]), "r"(b0), "r"(b1));
}
#define LDSM_X4(r, addr) \
    asm volatile("ldmatrix.sync.aligned.m8n8.x4.shared.b16 {%0,%1,%2,%3}, [%4];" \
        : "=r"((r)[0]), "=r"((r)[1]), "=r"((r)[2]), "=r"((r)[3]) : "r"(addr))
#define CP_ASYNC16(dst, src) \
    asm volatile("cp.async.cg.shared.global [%0], [%1], 16;" :: "r"(dst), "l"(src))
#define CP_COMMIT()  asm volatile("cp.async.commit_group;" ::: "memory")
#define CP_WAIT0()   asm volatile("cp.async.wait_group 0;"  ::: "memory")

#define B_BASE_OFF 34816u                 // A tile = 128*272 B
#define YST_OFF    104448u                // + B tile 69632
#define BST_OFF    139264u                // + y staging 128*272
#define SMEM_TOT   141440u                // + base staging 8*272

// ---------------- K3: persistent fp16 MLP, 512 thr (16 warps), cp.async ----
__global__ __launch_bounds__(512, 1) void mlp_kernel(const float* __restrict__ b2,
                                                     float* __restrict__ out) {
    extern __shared__ __align__(16) char dyn[];
    __shared__ int s_pts[2][8];
    __shared__ float sbias[Oq];

    const int tid = threadIdx.x, warp = tid >> 5, lane = tid & 31;
    const int t4 = lane & 3;
    const int pg = warp >> 2, nch = warp & 3, n0 = nch * 64;   // pg 0..3: 2 pts each
    const uint32_t sbase = smem_u32(dyn);

    {   // stage fp16 W2^T once per block
        const float4* sW = (const float4*)g_wH;
        float4* dW = (float4*)(dyn + B_BASE_OFF);
        for (int j = tid; j < Oq * LDH / 8; j += 512) dW[j] = sW[j];
    }
    if (tid < Oq) sbias[tid] = b2[tid];

    // ldmatrix base addresses (same validated fragment mapping, 2 A-tiles/warp)
    uint32_t aAddr[2];
    #pragma unroll
    for (int i = 0; i < 2; i++)
        aAddr[i] = sbase + ((pg * 2 + i) * 16 + (lane & 15)) * 272 + (lane >> 4) * 16;
    uint32_t bAddr[4];
    #pragma unroll
    for (int j = 0; j < 4; j++)
        bAddr[j] = sbase + B_BASE_OFF +
                   (n0 + j * 16 + (lane & 7) + ((lane >> 4) << 3)) * 272 +
                   ((lane >> 3) & 1) * 16;

    // staging mapping: r = A row (0..127), q = 64B quarter
    const int r = tid >> 2, q = tid & 3;
    const uint32_t yDst = sbase + YST_OFF + r * 272 + q * 64;
    const uint32_t bDst = sbase + BST_OFF + (tid >> 4) * 272 + (tid & 15) * 16;

    const int cnt = g_cnt, ngrp = (cnt + 7) >> 3, stride = gridDim.x;
    int grp = blockIdx.x;
    if (tid < 8 && grp < ngrp) s_pts[0][tid] = g_list[grp * 8 + tid];
    __syncthreads();    // W2 + sbias staged, s_pts[0] visible

    if (grp < ngrp) {   // prologue prefetch: 4x16B y per thread + base (tid<128)
        const int point = s_pts[0][r >> 4];
        const int nb = g_idx[point * Kq + (r & 15)];
        const char* src = (const char*)(g_y + (size_t)((point >> 7) * Pq + nb) * Hq) + q * 64;
        #pragma unroll
        for (int j = 0; j < 4; j++) CP_ASYNC16(yDst + 16 * j, src + 16 * j);
        if (tid < 128) {
            const char* bsrc = (const char*)(g_base + (size_t)s_pts[0][tid >> 4] * Hq) + (tid & 15) * 16;
            CP_ASYNC16(bDst, bsrc);
        }
    }
    CP_COMMIT();

    int par = 0;
    for (; grp < ngrp; grp += stride) {
        const int nxt = grp + stride;
        CP_WAIT0();
        __syncthreads();    // staging arrived; prev group's MMA/epilogue done

        {   // convert: A = hmax2(hadd2(y, base), 0)  (64B per thread)
            const char* yS = dyn + YST_OFF + r * 272 + q * 64;
            const char* bS = dyn + BST_OFF + (r >> 4) * 272 + q * 64;
            char* pA = dyn + r * 272 + q * 64;
            const __half2 z2 = __float2half2_rn(0.f);
            #pragma unroll
            for (int c = 0; c < 4; c++) {
                __half2 y0 = *(const __half2*)(yS + 16 * c);
                __half2 y1 = *(const __half2*)(yS + 16 * c + 4);
                __half2 y2 = *(const __half2*)(yS + 16 * c + 8);
                __half2 y3 = *(const __half2*)(yS + 16 * c + 12);
                __half2 b0 = *(const __half2*)(bS + 16 * c);
                __half2 b1v = *(const __half2*)(bS + 16 * c + 4);
                __half2 b2v = *(const __half2*)(bS + 16 * c + 8);
                __half2 b3 = *(const __half2*)(bS + 16 * c + 12);
                __half2 q0 = __hmax2(__hadd2(y0, b0), z2);
                __half2 q1 = __hmax2(__hadd2(y1, b1v), z2);
                __half2 q2 = __hmax2(__hadd2(y2, b2v), z2);
                __half2 q3 = __hmax2(__hadd2(y3, b3), z2);
                uint4 qv;
                qv.x = *(uint32_t*)&q0; qv.y = *(uint32_t*)&q1;
                qv.z = *(uint32_t*)&q2; qv.w = *(uint32_t*)&q3;
                *(uint4*)(pA + 16 * c) = qv;
            }
        }
        if (tid < 8 && nxt < ngrp) s_pts[par ^ 1][tid] = g_list[nxt * 8 + tid];
        __syncthreads();    // A ready; staging drained; s_pts[next] visible

        if (nxt < ngrp) {   // prefetch next group (overlaps MMA + epilogue)
            const int point = s_pts[par ^ 1][r >> 4];
            const int nb = g_idx[point * Kq + (r & 15)];
            const char* src = (const char*)(g_y + (size_t)((point >> 7) * Pq + nb) * Hq) + q * 64;
            #pragma unroll
            for (int j = 0; j < 4; j++) CP_ASYNC16(yDst + 16 * j, src + 16 * j);
            if (tid < 128) {
                const char* bsrc = (const char*)(g_base + (size_t)s_pts[par ^ 1][tid >> 4] * Hq) + (tid & 15) * 16;
                CP_ASYNC16(bDst, bsrc);
            }
        }
        CP_COMMIT();

        float acc[2][8][4];
        #pragma unroll
        for (int i = 0; i < 2; i++)
            #pragma unroll
            for (int nt = 0; nt < 8; nt++)
                #pragma unroll
                for (int c = 0; c < 4; c++) acc[i][nt][c] = 0.f;

        #pragma unroll 1
        for (int s = 0; s < 8; s++) {
            const uint32_t ks = s * 32;
            unsigned aF[2][4], bF[4][4];
            #pragma unroll
            for (int i = 0; i < 2; i++) LDSM_X4(aF[i], aAddr[i] + ks);
            #pragma unroll
            for (int j = 0; j < 4; j++) LDSM_X4(bF[j], bAddr[j] + ks);
            #pragma unroll
            for (int j = 0; j < 4; j++)
                #pragma unroll
                for (int i = 0; i < 2; i++) {
                    mma_f16(acc[i][2 * j],     aF[i], bF[j][0], bF[j][1]);
                    mma_f16(acc[i][2 * j + 1], aF[i], bF[j][2], bF[j][3]);
                }
        }

        // epilogue: relu(+bias from smem), mean over 16 edge rows, write out
        #pragma unroll
        for (int i = 0; i < 2; i++) {
            const int point = s_pts[par][pg * 2 + i];
            float* orow = out + (size_t)point * (Oq + 1);
            #pragma unroll
            for (int nt = 0; nt < 8; nt++) {
                const int col = n0 + nt * 8 + 2 * t4;
                const float bb0 = sbias[col], bb1 = sbias[col + 1];
                float s0 = fmaxf(acc[i][nt][0] + bb0, 0.f)
                         + fmaxf(acc[i][nt][2] + bb0, 0.f);
                float s1 = fmaxf(acc[i][nt][1] + bb1, 0.f)
                         + fmaxf(acc[i][nt][3] + bb1, 0.f);
                #pragma unroll
                for (int o = 4; o < 32; o <<= 1) {
                    s0 += __shfl_xor_sync(0xffffffffu, s0, o);
                    s1 += __shfl_xor_sync(0xffffffffu, s1, o);
                }
                if ((lane >> 2) == 0) {
                    orow[col]     = s0 * (1.f / 16.f);
                    orow[col + 1] = s1 * (1.f / 16.f);
                }
            }
            if (nch == 0 && lane == 0) orow[Oq] = 1.f;
        }
        par ^= 1;
    }
}

// ---------------------------------------------------------------------------
extern "C" void kernel_launch(void* const* d_in, const int* in_sizes, int n_in,
                              void* d_out, int out_size) {
    (void)in_sizes; (void)n_in; (void)out_size;
    const float* x  = (const float*)d_in[0];
    const float* W1 = (const float*)d_in[1];
    const float* b1 = (const float*)d_in[2];
    const float* W2 = (const float*)d_in[3];
    const float* b2 = (const float*)d_in[4];
    float* out = (float*)d_out;

    cudaFuncSetAttribute(mlp_kernel, cudaFuncAttributeMaxDynamicSharedMemorySize, SMEM_TOT);

    prep_kernel<<<256, 128>>>(W2);                  // resets g_cnt before embed's atomics
    knn_kernel<<<dim3(Bq, 2), 64>>>(x);
    embed_kernel<<<Bq * Pq / 8, 256>>>(x, W1, b1, out);
    mlp_kernel<<<148, 512, SMEM_TOT>>>(b2, out);
}